// round 1
// baseline (speedup 1.0000x reference)
#include <cuda_runtime.h>
#include <math.h>

#define NN 50000
#define EE 800000
#define FF 128
#define SRCD 32
#define EPS 1e-5f

// ---------------- scratch (static device globals; no allocs) ----------------
__device__ float    g_h1[NN * FF];     // x @ node_W1 + b1
__device__ float    g_sf[NN * FF];     // src_feats
__device__ float    g_nf[NN * FF];     // aggregated new_feats
__device__ float    g_ex[EE];          // logits, then exp values
__device__ unsigned g_smax[NN];        // per-dst max (ordered-uint encoding)
__device__ float    g_den[NN];         // per-dst softmax denominator
__device__ float    g_cs1[FF], g_cq1[FF];   // col stats of h1
__device__ float    g_cs2[FF], g_cq2[FF];   // col stats of new_feats
__device__ float    g_emom[20];             // edata sums: mu[4], pair moments[10]
__device__ float    g_ninv[FF], g_noff[FF]; // node LN fold
__device__ float    g_finv[FF], g_foff[FF]; // output LN fold
__device__ float    g_w1p[4 * FF], g_b1p[FF]; // edge W1/b1 with LN folded in

__device__ __forceinline__ float elu1(float x) { return x > 0.f ? x : expm1f(x); }

__device__ __forceinline__ unsigned fenc(float f) {
    unsigned u = __float_as_uint(f);
    return (u & 0x80000000u) ? ~u : (u | 0x80000000u);
}
__device__ __forceinline__ float fdec(unsigned u) {
    return (u & 0x80000000u) ? __uint_as_float(u & 0x7fffffffu) : __uint_as_float(~u);
}

// ---------------- zero init ----------------
__global__ void k_zero() {
    int i = blockIdx.x * blockDim.x + threadIdx.x;
    if (i < NN * FF) g_nf[i] = 0.f;
    if (i < NN) { g_smax[i] = 0u; g_den[i] = 0.f; }
    if (i < FF) { g_cs1[i] = 0.f; g_cq1[i] = 0.f; g_cs2[i] = 0.f; g_cq2[i] = 0.f; }
    if (i < 20) g_emom[i] = 0.f;
}

// ---------------- SGEMM: 64x128 tile, K=128 (+optional 32), fused LN+ELU on A ----------------
// MODE 0: C=g_h1 = A(x) @ B + bias
// MODE 1: C=g_sf = elu(ln(g_h1)) @ B + bias + A2(src_data) @ B2 + bias2
// MODE 2: C=out  = elu(ln(g_nf)) @ B + bias
template <int MODE>
__global__ void __launch_bounds__(256) k_gemm(
    const float* __restrict__ A_in, const float* __restrict__ B,
    const float* __restrict__ bias,
    const float* __restrict__ A2, const float* __restrict__ B2,
    const float* __restrict__ bias2,
    float* __restrict__ C_out)
{
    __shared__ __align__(16) float As[16][68];
    __shared__ __align__(16) float Bs[16][128];

    const int tid = threadIdx.x;
    const int tx = tid & 31, ty = tid >> 5;
    const int row0 = blockIdx.x * 64;
    const int ar = tid >> 2;          // 0..63
    const int ak = (tid & 3) * 4;     // 0,4,8,12
    const int arow = row0 + ar;
    const bool aval = arow < NN;
    const int bc = (tid & 31) * 4;
    const int br = tid >> 5;

    const float* A = (MODE == 0) ? A_in : (MODE == 1 ? g_h1 : g_nf);
    float* C = (MODE == 1) ? g_sf : ((MODE == 0) ? g_h1 : C_out);
    const float* ivp = (MODE == 1) ? g_ninv : g_finv;
    const float* ofp = (MODE == 1) ? g_noff : g_foff;

    float4 acc[8];
#pragma unroll
    for (int i = 0; i < 8; i++) acc[i] = make_float4(0.f, 0.f, 0.f, 0.f);

#pragma unroll 1
    for (int kt = 0; kt < 8; kt++) {
        const int k0 = kt * 16;
        float4 av = make_float4(0.f, 0.f, 0.f, 0.f);
        if (aval) av = *(const float4*)(A + (size_t)arow * FF + k0 + ak);
        if (MODE != 0) {
            const int kb = k0 + ak;
            av.x = elu1(fmaf(av.x, ivp[kb + 0], ofp[kb + 0]));
            av.y = elu1(fmaf(av.y, ivp[kb + 1], ofp[kb + 1]));
            av.z = elu1(fmaf(av.z, ivp[kb + 2], ofp[kb + 2]));
            av.w = elu1(fmaf(av.w, ivp[kb + 3], ofp[kb + 3]));
        }
        As[ak + 0][ar] = av.x; As[ak + 1][ar] = av.y;
        As[ak + 2][ar] = av.z; As[ak + 3][ar] = av.w;
        *(float4*)&Bs[br][bc]     = *(const float4*)(B + (size_t)(k0 + br) * FF + bc);
        *(float4*)&Bs[br + 8][bc] = *(const float4*)(B + (size_t)(k0 + br + 8) * FF + bc);
        __syncthreads();
#pragma unroll
        for (int k = 0; k < 16; k++) {
            float4 b = *(const float4*)&Bs[k][tx * 4];
            float4 a0 = *(const float4*)&As[k][ty * 8];
            float4 a1 = *(const float4*)&As[k][ty * 8 + 4];
            float a[8] = {a0.x, a0.y, a0.z, a0.w, a1.x, a1.y, a1.z, a1.w};
#pragma unroll
            for (int i = 0; i < 8; i++) {
                acc[i].x = fmaf(a[i], b.x, acc[i].x);
                acc[i].y = fmaf(a[i], b.y, acc[i].y);
                acc[i].z = fmaf(a[i], b.z, acc[i].z);
                acc[i].w = fmaf(a[i], b.w, acc[i].w);
            }
        }
        __syncthreads();
    }

    if (MODE == 1) {
#pragma unroll 1
        for (int kt = 0; kt < 2; kt++) {
            const int k0 = kt * 16;
            float4 av = make_float4(0.f, 0.f, 0.f, 0.f);
            if (aval) av = *(const float4*)(A2 + (size_t)arow * SRCD + k0 + ak);
            As[ak + 0][ar] = av.x; As[ak + 1][ar] = av.y;
            As[ak + 2][ar] = av.z; As[ak + 3][ar] = av.w;
            *(float4*)&Bs[br][bc]     = *(const float4*)(B2 + (size_t)(k0 + br) * FF + bc);
            *(float4*)&Bs[br + 8][bc] = *(const float4*)(B2 + (size_t)(k0 + br + 8) * FF + bc);
            __syncthreads();
#pragma unroll
            for (int k = 0; k < 16; k++) {
                float4 b = *(const float4*)&Bs[k][tx * 4];
                float4 a0 = *(const float4*)&As[k][ty * 8];
                float4 a1 = *(const float4*)&As[k][ty * 8 + 4];
                float a[8] = {a0.x, a0.y, a0.z, a0.w, a1.x, a1.y, a1.z, a1.w};
#pragma unroll
                for (int i = 0; i < 8; i++) {
                    acc[i].x = fmaf(a[i], b.x, acc[i].x);
                    acc[i].y = fmaf(a[i], b.y, acc[i].y);
                    acc[i].z = fmaf(a[i], b.z, acc[i].z);
                    acc[i].w = fmaf(a[i], b.w, acc[i].w);
                }
            }
            __syncthreads();
        }
    }

    float4 bv = *(const float4*)(bias + tx * 4);
    if (MODE == 1) {
        float4 b2v = *(const float4*)(bias2 + tx * 4);
        bv.x += b2v.x; bv.y += b2v.y; bv.z += b2v.z; bv.w += b2v.w;
    }
#pragma unroll
    for (int i = 0; i < 8; i++) {
        int r = row0 + ty * 8 + i;
        if (r < NN) {
            float4 o = make_float4(acc[i].x + bv.x, acc[i].y + bv.y,
                                   acc[i].z + bv.z, acc[i].w + bv.w);
            *(float4*)(C + (size_t)r * FF + tx * 4) = o;
        }
    }
}

// ---------------- column stats (sum, sumsq over rows) ----------------
template <int WHICH>
__global__ void k_colstats() {
    const float* A = (WHICH == 1) ? g_h1 : g_nf;
    float* S = (WHICH == 1) ? g_cs1 : g_cs2;
    float* Q = (WHICH == 1) ? g_cq1 : g_cq2;
    int c = threadIdx.x;  // 128
    float s = 0.f, q = 0.f;
    for (int r = blockIdx.x; r < NN; r += gridDim.x) {
        float v = A[(size_t)r * FF + c];
        s += v;
        q = fmaf(v, v, q);
    }
    atomicAdd(&S[c], s);
    atomicAdd(&Q[c], q);
}

// ---------------- edata moments: mu[4] sums + 10 pair-product sums ----------------
__global__ void k_emom(const float4* __restrict__ ed) {
    int tid = threadIdx.x;
    float s[4] = {0.f, 0.f, 0.f, 0.f};
    float m[10] = {0.f};
    for (int e = blockIdx.x * blockDim.x + tid; e < EE; e += gridDim.x * blockDim.x) {
        float4 v = ed[e];
        s[0] += v.x; s[1] += v.y; s[2] += v.z; s[3] += v.w;
        m[0] = fmaf(v.x, v.x, m[0]); m[1] = fmaf(v.x, v.y, m[1]);
        m[2] = fmaf(v.x, v.z, m[2]); m[3] = fmaf(v.x, v.w, m[3]);
        m[4] = fmaf(v.y, v.y, m[4]); m[5] = fmaf(v.y, v.z, m[5]);
        m[6] = fmaf(v.y, v.w, m[6]); m[7] = fmaf(v.z, v.z, m[7]);
        m[8] = fmaf(v.z, v.w, m[8]); m[9] = fmaf(v.w, v.w, m[9]);
    }
#pragma unroll
    for (int o = 16; o; o >>= 1) {
#pragma unroll
        for (int j = 0; j < 4; j++) s[j] += __shfl_down_sync(0xffffffffu, s[j], o);
#pragma unroll
        for (int j = 0; j < 10; j++) m[j] += __shfl_down_sync(0xffffffffu, m[j], o);
    }
    __shared__ float sm[14][8];
    int w = tid >> 5, l = tid & 31;
    if (l == 0) {
#pragma unroll
        for (int j = 0; j < 4; j++) sm[j][w] = s[j];
#pragma unroll
        for (int j = 0; j < 10; j++) sm[4 + j][w] = m[j];
    }
    __syncthreads();
    if (tid < 14) {
        float acc = 0.f;
#pragma unroll
        for (int w2 = 0; w2 < 8; w2++) acc += sm[tid][w2];
        atomicAdd(&g_emom[tid], acc);
    }
}

// ---------------- prep1: node LN fold + analytic edge LN fold ----------------
__global__ void k_prep1(const float* __restrict__ node_g, const float* __restrict__ node_be,
                        const float* __restrict__ eW1, const float* __restrict__ eb1,
                        const float* __restrict__ eg, const float* __restrict__ ebe) {
    int c = threadIdx.x;  // 128
    // node LN (stats of g_h1 over rows)
    float m = g_cs1[c] * (1.f / NN);
    float v = fmaxf(g_cq1[c] * (1.f / NN) - m * m, 0.f);
    float inv = node_g[c] / (sqrtf(v) + EPS);
    g_ninv[c] = inv;
    g_noff[c] = node_be[c] - m * inv;

    // edge LN: t = edata@W1 + b1; stats from edata moments (exact, linear map)
    const int PIDX[4][4] = {{4, 5, 6, 7}, {5, 8, 9, 10}, {6, 9, 11, 12}, {7, 10, 12, 13}};
    float A[4], mu[4];
#pragma unroll
    for (int d = 0; d < 4; d++) {
        A[d] = eW1[d * FF + c];
        mu[d] = g_emom[d] * (1.f / EE);
    }
    float b1 = eb1[c];
    float dotmu = 0.f;
#pragma unroll
    for (int d = 0; d < 4; d++) dotmu += mu[d] * A[d];
    float em = b1 + dotmu;
    float e2 = b1 * b1 + 2.f * b1 * dotmu;
#pragma unroll
    for (int d = 0; d < 4; d++)
#pragma unroll
        for (int d2 = 0; d2 < 4; d2++)
            e2 += A[d] * A[d2] * (g_emom[PIDX[d][d2]] * (1.f / EE));
    float ev = fmaxf(e2 - em * em, 0.f);
    float einv = eg[c] / (sqrtf(ev) + EPS);
    float eoff = ebe[c] - em * einv;
#pragma unroll
    for (int d = 0; d < 4; d++) g_w1p[d * FF + c] = A[d] * einv;
    g_b1p[c] = b1 * einv + eoff;
}

// ---------------- prep2: output LN fold ----------------
__global__ void k_prep2(const float* __restrict__ out_g, const float* __restrict__ out_be) {
    int c = threadIdx.x;
    float m = g_cs2[c] * (1.f / NN);
    float v = fmaxf(g_cq2[c] * (1.f / NN) - m * m, 0.f);
    float inv = out_g[c] / (sqrtf(v) + EPS);
    g_finv[c] = inv;
    g_foff[c] = out_be[c] - m * inv;
}

// ---------------- per-edge logits + segment max ----------------
__global__ void __launch_bounds__(256) k_elogit(const float4* __restrict__ ed4,
                                                const float* __restrict__ eW2,
                                                const float* __restrict__ eb2,
                                                const int* __restrict__ dst) {
    __shared__ __align__(16) float sw[4 * FF];
    __shared__ __align__(16) float sb[FF];
    __shared__ __align__(16) float s2[FF];
    int tid = threadIdx.x;
    for (int i = tid; i < 4 * FF; i += blockDim.x) sw[i] = g_w1p[i];
    for (int i = tid; i < FF; i += blockDim.x) { sb[i] = g_b1p[i]; s2[i] = eW2[i]; }
    __syncthreads();

    int e = blockIdx.x * blockDim.x + tid;
    if (e >= EE) return;
    float4 v = ed4[e];
    float acc = 0.f;
#pragma unroll
    for (int c = 0; c < FF; c += 4) {
        float4 w0 = *(const float4*)&sw[c];
        float4 w1 = *(const float4*)&sw[FF + c];
        float4 w2 = *(const float4*)&sw[2 * FF + c];
        float4 w3 = *(const float4*)&sw[3 * FF + c];
        float4 bb = *(const float4*)&sb[c];
        float4 ww = *(const float4*)&s2[c];
        float t0 = bb.x + v.x * w0.x + v.y * w1.x + v.z * w2.x + v.w * w3.x;
        float t1 = bb.y + v.x * w0.y + v.y * w1.y + v.z * w2.y + v.w * w3.y;
        float t2 = bb.z + v.x * w0.z + v.y * w1.z + v.z * w2.z + v.w * w3.z;
        float t3 = bb.w + v.x * w0.w + v.y * w1.w + v.z * w2.w + v.w * w3.w;
        acc = fmaf(elu1(t0), ww.x, acc);
        acc = fmaf(elu1(t1), ww.y, acc);
        acc = fmaf(elu1(t2), ww.z, acc);
        acc = fmaf(elu1(t3), ww.w, acc);
    }
    acc += eb2[0];
    g_ex[e] = acc;
    atomicMax(&g_smax[dst[e]], fenc(acc));
}

// ---------------- exp + segment denominator ----------------
__global__ void k_exp(const int* __restrict__ dst) {
    int e = blockIdx.x * blockDim.x + threadIdx.x;
    if (e >= EE) return;
    int d = dst[e];
    float ex = expf(g_ex[e] - fdec(g_smax[d]));
    g_ex[e] = ex;
    atomicAdd(&g_den[d], ex);
}

// ---------------- gather + weight + scatter (warp per edge, float4 RED) ----------------
__global__ void __launch_bounds__(256) k_scatter(const int* __restrict__ src,
                                                 const int* __restrict__ dst) {
    int gw = (blockIdx.x * blockDim.x + threadIdx.x) >> 5;
    int lane = threadIdx.x & 31;
    if (gw >= EE) return;
    int s = src[gw], d = dst[gw];
    float a = g_ex[gw] / g_den[d];
    const float4* sf4 = (const float4*)g_sf;
    float4 v = sf4[(size_t)s * 32 + lane];
    float4 r = make_float4(v.x * a, v.y * a, v.z * a, v.w * a);
    atomicAdd(((float4*)g_nf) + (size_t)d * 32 + lane, r);
}

// ---------------- launch ----------------
extern "C" void kernel_launch(void* const* d_in, const int* in_sizes, int n_in,
                              void* d_out, int out_size) {
    const float* x         = (const float*)d_in[0];
    const float* src_data  = (const float*)d_in[1];
    const float* edata     = (const float*)d_in[2];
    const int*   src_idx   = (const int*)d_in[3];
    const int*   dst_idx   = (const int*)d_in[4];
    const float* lin_src_W = (const float*)d_in[5];
    const float* lin_src_b = (const float*)d_in[6];
    const float* node_W1   = (const float*)d_in[7];
    const float* node_b1   = (const float*)d_in[8];
    const float* node_g    = (const float*)d_in[9];
    const float* node_be   = (const float*)d_in[10];
    const float* node_W2   = (const float*)d_in[11];
    const float* node_b2   = (const float*)d_in[12];
    const float* edge_W1   = (const float*)d_in[13];
    const float* edge_b1   = (const float*)d_in[14];
    const float* edge_g    = (const float*)d_in[15];
    const float* edge_be   = (const float*)d_in[16];
    const float* edge_W2   = (const float*)d_in[17];
    const float* edge_b2   = (const float*)d_in[18];
    const float* out_g     = (const float*)d_in[19];
    const float* out_be    = (const float*)d_in[20];
    const float* out_W     = (const float*)d_in[21];
    const float* out_b     = (const float*)d_in[22];
    float* out = (float*)d_out;

    const int GEMM_BLOCKS = (NN + 63) / 64;  // 782

    k_zero<<<(NN * FF + 255) / 256, 256>>>();

    // node path: h1 = x @ W1 + b1
    k_gemm<0><<<GEMM_BLOCKS, 256>>>(x, node_W1, node_b1, nullptr, nullptr, nullptr, nullptr);
    k_colstats<1><<<512, 128>>>();

    // edge path stats (runs on edata only)
    k_emom<<<512, 256>>>((const float4*)edata);
    k_prep1<<<1, 128>>>(node_g, node_be, edge_W1, edge_b1, edge_g, edge_be);

    // src_feats = elu(ln(h1)) @ W2 + b2 + src_data @ lin_src_W + lin_src_b
    k_gemm<1><<<GEMM_BLOCKS, 256>>>(nullptr, node_W2, node_b2, src_data, lin_src_W,
                                    lin_src_b, nullptr);

    // per-edge logits + segment softmax
    k_elogit<<<(EE + 255) / 256, 256>>>((const float4*)edata, edge_W2, edge_b2, dst_idx);
    k_exp<<<(EE + 255) / 256, 256>>>(dst_idx);

    // message passing
    k_scatter<<<(EE * 32 + 255) / 256, 256>>>(src_idx, dst_idx);

    // output: elu(ln(new_feats)) @ out_W + out_b
    k_colstats<2><<<512, 128>>>();
    k_prep2<<<1, 128>>>(out_g, out_be);
    k_gemm<2><<<GEMM_BLOCKS, 256>>>(nullptr, out_W, out_b, nullptr, nullptr, nullptr, out);
}

// round 3
// speedup vs baseline: 1.0402x; 1.0402x over previous
#include <cuda_runtime.h>
#include <math.h>

#define NN 50000
#define EE 800000
#define FF 128
#define SRCD 32
#define EPS 1e-5f

// ---------------- scratch (static device globals; no allocs) ----------------
__device__ float g_h1[NN * FF];        // x @ node_W1 + b1
__device__ float g_sf[NN * FF];        // src_feats
__device__ float g_nf[NN * FF];        // aggregated new_feats
__device__ float g_logit[EE];          // per-edge logits, then exp values
__device__ int   g_cnt[NN];            // per-dst degree
__device__ int   g_off[NN + 1];        // CSR offsets
__device__ int   g_pos[NN];            // fill cursors
__device__ int   g_eid[EE];            // edge ids sorted by dst
__device__ float g_cs1[FF], g_cq1[FF]; // col stats of h1
__device__ float g_cs2[FF], g_cq2[FF]; // col stats of new_feats
__device__ float g_emom[20];           // edata sums: mu[4], pair moments[10]
__device__ float g_ninv[FF], g_noff[FF];
__device__ float g_finv[FF], g_foff[FF];
__device__ float g_w1p[4 * FF], g_b1p[FF];

__device__ __forceinline__ float elu1(float x) {
    return x > 0.f ? x : (__expf(x) - 1.f);
}

// ---------------- zero small scratch ----------------
__global__ void k_zero() {
    int i = blockIdx.x * blockDim.x + threadIdx.x;
    if (i < NN) g_cnt[i] = 0;
    if (i < FF) { g_cs1[i] = 0.f; g_cq1[i] = 0.f; g_cs2[i] = 0.f; g_cq2[i] = 0.f; }
    if (i < 20) g_emom[i] = 0.f;
}

// ---------------- SGEMM 128x128x16, 8x8 per thread, fused LN+ELU on A -------
// MODE 0: C=g_h1 = A(x) @ B + bias                  (+fused column stats)
// MODE 1: C=g_sf = elu(ln(g_h1)) @ B + bias + A2(src_data) @ B2 + bias2
// MODE 2: C=out  = elu(ln(g_nf)) @ B + bias
template <int MODE>
__global__ void __launch_bounds__(256) k_gemm(
    const float* __restrict__ A_in, const float* __restrict__ B,
    const float* __restrict__ bias,
    const float* __restrict__ A2, const float* __restrict__ B2,
    const float* __restrict__ bias2,
    float* __restrict__ C_out)
{
    __shared__ __align__(16) float As[16][132];
    __shared__ __align__(16) float Bs[16][128];
    __shared__ float ss[FF], sq[FF];

    const int tid = threadIdx.x;
    const int tx = tid & 15, ty = tid >> 4;      // 16x16 thread grid
    const int row0 = blockIdx.x * 128;
    const int ar = tid >> 2;                      // 0..63
    const int ak = (tid & 3) * 4;                 // 0,4,8,12
    const int bc = (tid & 31) * 4;
    const int br = tid >> 5;

    if (MODE == 0 && tid < FF) { ss[tid] = 0.f; sq[tid] = 0.f; }

    const float* A = (MODE == 0) ? A_in : (MODE == 1 ? g_h1 : g_nf);
    float* C = (MODE == 1) ? g_sf : ((MODE == 0) ? g_h1 : C_out);
    const float* ivp = (MODE == 1) ? g_ninv : g_finv;
    const float* ofp = (MODE == 1) ? g_noff : g_foff;

    float acc[8][8];
#pragma unroll
    for (int i = 0; i < 8; i++)
#pragma unroll
        for (int j = 0; j < 8; j++) acc[i][j] = 0.f;

#pragma unroll 1
    for (int kt = 0; kt < 8; kt++) {
        const int k0 = kt * 16;
#pragma unroll
        for (int h = 0; h < 2; h++) {
            int row = row0 + ar + h * 64;
            float4 av = make_float4(0.f, 0.f, 0.f, 0.f);
            if (row < NN) av = *(const float4*)(A + (size_t)row * FF + k0 + ak);
            if (MODE != 0) {
                const int kb = k0 + ak;
                av.x = elu1(fmaf(av.x, ivp[kb + 0], ofp[kb + 0]));
                av.y = elu1(fmaf(av.y, ivp[kb + 1], ofp[kb + 1]));
                av.z = elu1(fmaf(av.z, ivp[kb + 2], ofp[kb + 2]));
                av.w = elu1(fmaf(av.w, ivp[kb + 3], ofp[kb + 3]));
            }
            As[ak + 0][ar + h * 64] = av.x; As[ak + 1][ar + h * 64] = av.y;
            As[ak + 2][ar + h * 64] = av.z; As[ak + 3][ar + h * 64] = av.w;
            *(float4*)&Bs[br + h * 8][bc] =
                *(const float4*)(B + (size_t)(k0 + br + h * 8) * FF + bc);
        }
        __syncthreads();
#pragma unroll
        for (int k = 0; k < 16; k++) {
            float4 a0 = *(const float4*)&As[k][ty * 8];
            float4 a1 = *(const float4*)&As[k][ty * 8 + 4];
            float4 b0 = *(const float4*)&Bs[k][tx * 8];
            float4 b1 = *(const float4*)&Bs[k][tx * 8 + 4];
            float a[8] = {a0.x, a0.y, a0.z, a0.w, a1.x, a1.y, a1.z, a1.w};
            float b[8] = {b0.x, b0.y, b0.z, b0.w, b1.x, b1.y, b1.z, b1.w};
#pragma unroll
            for (int i = 0; i < 8; i++)
#pragma unroll
                for (int j = 0; j < 8; j++)
                    acc[i][j] = fmaf(a[i], b[j], acc[i][j]);
        }
        __syncthreads();
    }

    if (MODE == 1) {
#pragma unroll 1
        for (int kt = 0; kt < 2; kt++) {
            const int k0 = kt * 16;
#pragma unroll
            for (int h = 0; h < 2; h++) {
                int row = row0 + ar + h * 64;
                float4 av = make_float4(0.f, 0.f, 0.f, 0.f);
                if (row < NN) av = *(const float4*)(A2 + (size_t)row * SRCD + k0 + ak);
                As[ak + 0][ar + h * 64] = av.x; As[ak + 1][ar + h * 64] = av.y;
                As[ak + 2][ar + h * 64] = av.z; As[ak + 3][ar + h * 64] = av.w;
                *(float4*)&Bs[br + h * 8][bc] =
                    *(const float4*)(B2 + (size_t)(k0 + br + h * 8) * FF + bc);
            }
            __syncthreads();
#pragma unroll
            for (int k = 0; k < 16; k++) {
                float4 a0 = *(const float4*)&As[k][ty * 8];
                float4 a1 = *(const float4*)&As[k][ty * 8 + 4];
                float4 b0 = *(const float4*)&Bs[k][tx * 8];
                float4 b1 = *(const float4*)&Bs[k][tx * 8 + 4];
                float a[8] = {a0.x, a0.y, a0.z, a0.w, a1.x, a1.y, a1.z, a1.w};
                float b[8] = {b0.x, b0.y, b0.z, b0.w, b1.x, b1.y, b1.z, b1.w};
#pragma unroll
                for (int i = 0; i < 8; i++)
#pragma unroll
                    for (int j = 0; j < 8; j++)
                        acc[i][j] = fmaf(a[i], b[j], acc[i][j]);
            }
            __syncthreads();
        }
    }

    float bv[8];
#pragma unroll
    for (int j = 0; j < 8; j += 4) {
        float4 t = *(const float4*)(bias + tx * 8 + j);
        bv[j] = t.x; bv[j + 1] = t.y; bv[j + 2] = t.z; bv[j + 3] = t.w;
    }
    if (MODE == 1) {
#pragma unroll
        for (int j = 0; j < 8; j += 4) {
            float4 t = *(const float4*)(bias2 + tx * 8 + j);
            bv[j] += t.x; bv[j + 1] += t.y; bv[j + 2] += t.z; bv[j + 3] += t.w;
        }
    }
#pragma unroll
    for (int i = 0; i < 8; i++) {
        int r = row0 + ty * 8 + i;
        if (r < NN) {
            float o[8];
#pragma unroll
            for (int j = 0; j < 8; j++) o[j] = acc[i][j] + bv[j];
            *(float4*)(C + (size_t)r * FF + tx * 8)     = make_float4(o[0], o[1], o[2], o[3]);
            *(float4*)(C + (size_t)r * FF + tx * 8 + 4) = make_float4(o[4], o[5], o[6], o[7]);
            if (MODE == 0) {
#pragma unroll
                for (int j = 0; j < 8; j++) {
                    atomicAdd(&ss[tx * 8 + j], o[j]);
                    atomicAdd(&sq[tx * 8 + j], o[j] * o[j]);
                }
            }
        }
    }
    if (MODE == 0) {
        __syncthreads();
        if (tid < FF) {
            atomicAdd(&g_cs1[tid], ss[tid]);
            atomicAdd(&g_cq1[tid], sq[tid]);
        }
    }
}

// ---------------- edata moments ----------------
__global__ void k_emom(const float4* __restrict__ ed) {
    int tid = threadIdx.x;
    float s[4] = {0.f, 0.f, 0.f, 0.f};
    float m[10] = {0.f};
    for (int e = blockIdx.x * blockDim.x + tid; e < EE; e += gridDim.x * blockDim.x) {
        float4 v = ed[e];
        s[0] += v.x; s[1] += v.y; s[2] += v.z; s[3] += v.w;
        m[0] = fmaf(v.x, v.x, m[0]); m[1] = fmaf(v.x, v.y, m[1]);
        m[2] = fmaf(v.x, v.z, m[2]); m[3] = fmaf(v.x, v.w, m[3]);
        m[4] = fmaf(v.y, v.y, m[4]); m[5] = fmaf(v.y, v.z, m[5]);
        m[6] = fmaf(v.y, v.w, m[6]); m[7] = fmaf(v.z, v.z, m[7]);
        m[8] = fmaf(v.z, v.w, m[8]); m[9] = fmaf(v.w, v.w, m[9]);
    }
#pragma unroll
    for (int o = 16; o; o >>= 1) {
#pragma unroll
        for (int j = 0; j < 4; j++) s[j] += __shfl_down_sync(0xffffffffu, s[j], o);
#pragma unroll
        for (int j = 0; j < 10; j++) m[j] += __shfl_down_sync(0xffffffffu, m[j], o);
    }
    __shared__ float sm[14][8];
    int w = tid >> 5, l = tid & 31;
    if (l == 0) {
#pragma unroll
        for (int j = 0; j < 4; j++) sm[j][w] = s[j];
#pragma unroll
        for (int j = 0; j < 10; j++) sm[4 + j][w] = m[j];
    }
    __syncthreads();
    if (tid < 14) {
        float acc = 0.f;
#pragma unroll
        for (int w2 = 0; w2 < 8; w2++) acc += sm[tid][w2];
        atomicAdd(&g_emom[tid], acc);
    }
}

// ---------------- prep1: node LN fold + analytic edge LN fold ----------------
__global__ void k_prep1(const float* __restrict__ node_g, const float* __restrict__ node_be,
                        const float* __restrict__ eW1, const float* __restrict__ eb1,
                        const float* __restrict__ eg, const float* __restrict__ ebe) {
    int c = threadIdx.x;
    float m = g_cs1[c] * (1.f / NN);
    float v = fmaxf(g_cq1[c] * (1.f / NN) - m * m, 0.f);
    float inv = node_g[c] / (sqrtf(v) + EPS);
    g_ninv[c] = inv;
    g_noff[c] = node_be[c] - m * inv;

    const int PIDX[4][4] = {{4, 5, 6, 7}, {5, 8, 9, 10}, {6, 9, 11, 12}, {7, 10, 12, 13}};
    float A[4], mu[4];
#pragma unroll
    for (int d = 0; d < 4; d++) {
        A[d] = eW1[d * FF + c];
        mu[d] = g_emom[d] * (1.f / EE);
    }
    float b1 = eb1[c];
    float dotmu = 0.f;
#pragma unroll
    for (int d = 0; d < 4; d++) dotmu += mu[d] * A[d];
    float em = b1 + dotmu;
    float e2 = b1 * b1 + 2.f * b1 * dotmu;
#pragma unroll
    for (int d = 0; d < 4; d++)
#pragma unroll
        for (int d2 = 0; d2 < 4; d2++)
            e2 += A[d] * A[d2] * (g_emom[PIDX[d][d2]] * (1.f / EE));
    float ev = fmaxf(e2 - em * em, 0.f);
    float einv = eg[c] / (sqrtf(ev) + EPS);
    float eoff = ebe[c] - em * einv;
#pragma unroll
    for (int d = 0; d < 4; d++) g_w1p[d * FF + c] = A[d] * einv;
    g_b1p[c] = b1 * einv + eoff;
}

// ---------------- prep2: output LN fold ----------------
__global__ void k_prep2(const float* __restrict__ out_g, const float* __restrict__ out_be) {
    int c = threadIdx.x;
    float m = g_cs2[c] * (1.f / NN);
    float v = fmaxf(g_cq2[c] * (1.f / NN) - m * m, 0.f);
    float inv = out_g[c] / (sqrtf(v) + EPS);
    g_finv[c] = inv;
    g_foff[c] = out_be[c] - m * inv;
}

// ---------------- per-edge logits + degree count ----------------
__global__ void __launch_bounds__(256) k_elogit(const float4* __restrict__ ed4,
                                                const float* __restrict__ eW2,
                                                const float* __restrict__ eb2,
                                                const int* __restrict__ dst) {
    __shared__ __align__(16) float sw[4 * FF];
    __shared__ __align__(16) float sb[FF];
    __shared__ __align__(16) float s2[FF];
    int tid = threadIdx.x;
    for (int i = tid; i < 4 * FF; i += blockDim.x) sw[i] = g_w1p[i];
    for (int i = tid; i < FF; i += blockDim.x) { sb[i] = g_b1p[i]; s2[i] = eW2[i]; }
    __syncthreads();

    int e = blockIdx.x * blockDim.x + tid;
    if (e >= EE) return;
    float4 v = ed4[e];
    float acc = 0.f;
#pragma unroll
    for (int c = 0; c < FF; c += 4) {
        float4 w0 = *(const float4*)&sw[c];
        float4 w1 = *(const float4*)&sw[FF + c];
        float4 w2 = *(const float4*)&sw[2 * FF + c];
        float4 w3 = *(const float4*)&sw[3 * FF + c];
        float4 bb = *(const float4*)&sb[c];
        float4 ww = *(const float4*)&s2[c];
        float t0 = bb.x + v.x * w0.x + v.y * w1.x + v.z * w2.x + v.w * w3.x;
        float t1 = bb.y + v.x * w0.y + v.y * w1.y + v.z * w2.y + v.w * w3.y;
        float t2 = bb.z + v.x * w0.z + v.y * w1.z + v.z * w2.z + v.w * w3.z;
        float t3 = bb.w + v.x * w0.w + v.y * w1.w + v.z * w2.w + v.w * w3.w;
        acc = fmaf(elu1(t0), ww.x, acc);
        acc = fmaf(elu1(t1), ww.y, acc);
        acc = fmaf(elu1(t2), ww.z, acc);
        acc = fmaf(elu1(t3), ww.w, acc);
    }
    acc += eb2[0];
    g_logit[e] = acc;
    atomicAdd(&g_cnt[dst[e]], 1);
}

// ---------------- exclusive scan of degrees (single block) ----------------
__global__ void __launch_bounds__(1024) k_scan() {
    __shared__ int sh[1024];
    int tid = threadIdx.x;
    const int CH = (NN + 1023) / 1024;  // 49
    int base = tid * CH;
    int s = 0;
    for (int j = 0; j < CH; j++) {
        int i = base + j;
        if (i < NN) s += g_cnt[i];
    }
    sh[tid] = s;
    __syncthreads();
    for (int o = 1; o < 1024; o <<= 1) {
        int v = (tid >= o) ? sh[tid - o] : 0;
        __syncthreads();
        sh[tid] += v;
        __syncthreads();
    }
    int pre = (tid == 0) ? 0 : sh[tid - 1];
    for (int j = 0; j < CH; j++) {
        int i = base + j;
        if (i < NN) {
            g_off[i] = pre;
            g_pos[i] = pre;
            pre += g_cnt[i];
        }
    }
    if (tid == 1023) g_off[NN] = sh[1023];
}

// ---------------- fill CSR edge list ----------------
__global__ void k_fill(const int* __restrict__ dst) {
    int e = blockIdx.x * blockDim.x + threadIdx.x;
    if (e >= EE) return;
    int p = atomicAdd(&g_pos[dst[e]], 1);
    g_eid[p] = e;
}

// ---------------- per-dst: softmax + gather + aggregate + fused stats -------
__global__ void __launch_bounds__(256) k_agg(const int* __restrict__ src) {
    __shared__ float ss[FF], sq[FF];
    int tid = threadIdx.x;
    int lane = tid & 31;
    int wid = tid >> 5;
    if (tid < FF) { ss[tid] = 0.f; sq[tid] = 0.f; }
    __syncthreads();

    int d = blockIdx.x * 8 + wid;
    float4 acc = make_float4(0.f, 0.f, 0.f, 0.f);
    if (d < NN) {
        int beg = g_off[d], end = g_off[d + 1];
        // pass 1: max
        float mx = -3.4e38f;
        for (int i = beg + lane; i < end; i += 32) mx = fmaxf(mx, g_logit[g_eid[i]]);
#pragma unroll
        for (int o = 16; o; o >>= 1) mx = fmaxf(mx, __shfl_xor_sync(0xffffffffu, mx, o));
        // pass 2: denominator; cache exp back into g_logit (edge owned by this warp)
        float den = 0.f;
        for (int i = beg + lane; i < end; i += 32) {
            int e = g_eid[i];
            float ex = __expf(g_logit[e] - mx);
            g_logit[e] = ex;
            den += ex;
        }
#pragma unroll
        for (int o = 16; o; o >>= 1) den += __shfl_xor_sync(0xffffffffu, den, o);
        float rden = den > 0.f ? 1.f / den : 0.f;
        __syncwarp();
        // pass 3: weighted gather
        const float4* sf4 = (const float4*)g_sf;
        for (int i = beg; i < end; i++) {
            int e = g_eid[i];
            float w = g_logit[e] * rden;
            float4 v = sf4[(size_t)src[e] * 32 + lane];
            acc.x = fmaf(w, v.x, acc.x);
            acc.y = fmaf(w, v.y, acc.y);
            acc.z = fmaf(w, v.z, acc.z);
            acc.w = fmaf(w, v.w, acc.w);
        }
        ((float4*)g_nf)[(size_t)d * 32 + lane] = acc;
        atomicAdd(&ss[lane * 4 + 0], acc.x);
        atomicAdd(&ss[lane * 4 + 1], acc.y);
        atomicAdd(&ss[lane * 4 + 2], acc.z);
        atomicAdd(&ss[lane * 4 + 3], acc.w);
        atomicAdd(&sq[lane * 4 + 0], acc.x * acc.x);
        atomicAdd(&sq[lane * 4 + 1], acc.y * acc.y);
        atomicAdd(&sq[lane * 4 + 2], acc.z * acc.z);
        atomicAdd(&sq[lane * 4 + 3], acc.w * acc.w);
    }
    __syncthreads();
    if (tid < FF) {
        atomicAdd(&g_cs2[tid], ss[tid]);
        atomicAdd(&g_cq2[tid], sq[tid]);
    }
}

// ---------------- launch ----------------
extern "C" void kernel_launch(void* const* d_in, const int* in_sizes, int n_in,
                              void* d_out, int out_size) {
    const float* x         = (const float*)d_in[0];
    const float* src_data  = (const float*)d_in[1];
    const float* edata     = (const float*)d_in[2];
    const int*   src_idx   = (const int*)d_in[3];
    const int*   dst_idx   = (const int*)d_in[4];
    const float* lin_src_W = (const float*)d_in[5];
    const float* lin_src_b = (const float*)d_in[6];
    const float* node_W1   = (const float*)d_in[7];
    const float* node_b1   = (const float*)d_in[8];
    const float* node_g    = (const float*)d_in[9];
    const float* node_be   = (const float*)d_in[10];
    const float* node_W2   = (const float*)d_in[11];
    const float* node_b2   = (const float*)d_in[12];
    const float* edge_W1   = (const float*)d_in[13];
    const float* edge_b1   = (const float*)d_in[14];
    const float* edge_g    = (const float*)d_in[15];
    const float* edge_be   = (const float*)d_in[16];
    const float* edge_W2   = (const float*)d_in[17];
    const float* edge_b2   = (const float*)d_in[18];
    const float* out_g     = (const float*)d_in[19];
    const float* out_be    = (const float*)d_in[20];
    const float* out_W     = (const float*)d_in[21];
    const float* out_b     = (const float*)d_in[22];
    float* out = (float*)d_out;

    const int GEMM_BLOCKS = (NN + 127) / 128;  // 391

    k_zero<<<(NN + 255) / 256, 256>>>();

    // node path: h1 = x @ W1 + b1 (+ fused column stats of h1)
    k_gemm<0><<<GEMM_BLOCKS, 256>>>(x, node_W1, node_b1, nullptr, nullptr, nullptr, nullptr);

    // edge-path analytic LN fold
    k_emom<<<512, 256>>>((const float4*)edata);
    k_prep1<<<1, 128>>>(node_g, node_be, edge_W1, edge_b1, edge_g, edge_be);

    // src_feats = elu(ln(h1)) @ W2 + b2 + src_data @ lin_src_W + lin_src_b
    k_gemm<1><<<GEMM_BLOCKS, 256>>>(nullptr, node_W2, node_b2, src_data, lin_src_W,
                                    lin_src_b, nullptr);

    // per-edge logits + degree counts
    k_elogit<<<(EE + 255) / 256, 256>>>((const float4*)edata, edge_W2, edge_b2, dst_idx);

    // CSR build
    k_scan<<<1, 1024>>>();
    k_fill<<<(EE + 255) / 256, 256>>>(dst_idx);

    // fused softmax + gather + aggregate + output-LN stats
    k_agg<<<(NN + 7) / 8, 256>>>(src_idx);

    // output: elu(ln(new_feats)) @ out_W + out_b
    k_prep2<<<1, 128>>>(out_g, out_be);
    k_gemm<2><<<GEMM_BLOCKS, 256>>>(nullptr, out_W, out_b, nullptr, nullptr, nullptr, out);
}